// round 1
// baseline (speedup 1.0000x reference)
#include <cuda_runtime.h>

#define HH 256
#define WW 256
#define BB 16
#define CC 32
#define OO 32

#define TH 8
#define TW 32
#define HALO 8
#define SB_ROWS (TH + 2*HALO)          // 24
#define SB_COLS (TW + 2*HALO)          // 48
#define SB_PLANE (SB_ROWS * SB_COLS)   // 1152
#define SB_FLOATS (CC * SB_PLANE)      // 36864
#define SW_FLOATS (9 * 32 * 32)        // 9216
#define DEFORM_SMEM ((SB_FLOATS + SW_FLOATS) * 4)  // 184320 B

// Scratch for the blurred image (B,C,H,W) fp32 = 134 MB
__device__ float g_blur[(size_t)BB * CC * HH * WW];

// ---------------- packed f32x2 helpers (Blackwell) ----------------
__device__ __forceinline__ unsigned long long pack2(float lo, float hi) {
    unsigned long long r;
    asm("mov.b64 %0, {%1, %2};" : "=l"(r) : "f"(lo), "f"(hi));
    return r;
}
__device__ __forceinline__ unsigned long long fma2(unsigned long long a,
                                                   unsigned long long b,
                                                   unsigned long long c) {
    unsigned long long d;
    asm("fma.rn.f32x2 %0, %1, %2, %3;" : "=l"(d) : "l"(a), "l"(b), "l"(c));
    return d;
}
__device__ __forceinline__ void unpack2(unsigned long long v, float& lo, float& hi) {
    asm("mov.b64 {%0, %1}, %2;" : "=f"(lo), "=f"(hi) : "l"(v));
}

// ---------------- Kernel 1: 5x5 gaussian blur (depthwise, SAME/zero pad) ----------------
__global__ __launch_bounds__(256) void blur_kernel(const float* __restrict__ x,
                                                   const float* __restrict__ sigp) {
    __shared__ float tile[36][36];
    const float sigma = *sigp;
    float wv[5];
    float s = 0.f;
#pragma unroll
    for (int i = 0; i < 5; i++) {
        float cc = (float)(i - 2);
        wv[i] = expf(-cc * cc / (2.f * sigma * sigma));
        s += wv[i];
    }
    const float inv_s2 = 1.f / (s * s);

    const int plane = blockIdx.z;                  // b*CC + c
    const int gy0 = blockIdx.y * 32 - 2;
    const int gx0 = blockIdx.x * 32 - 2;
    const float* xp = x + (size_t)plane * (HH * WW);
    const int tid = threadIdx.x + threadIdx.y * 32;  // block (32,8)

    for (int idx = tid; idx < 36 * 36; idx += 256) {
        int r = idx / 36, q = idx - r * 36;
        int gy = gy0 + r, gx = gx0 + q;
        float v = 0.f;
        if (gy >= 0 && gy < HH && gx >= 0 && gx < WW) v = xp[gy * WW + gx];
        tile[r][q] = v;
    }
    __syncthreads();

    float* op = g_blur + (size_t)plane * (HH * WW);
#pragma unroll
    for (int ry = 0; ry < 4; ry++) {
        const int row = threadIdx.y + ry * 8;
        float acc = 0.f;
#pragma unroll
        for (int i = 0; i < 5; i++) {
            float rs = 0.f;
#pragma unroll
            for (int j = 0; j < 5; j++)
                rs = fmaf(wv[j], tile[row + i][threadIdx.x + j], rs);
            acc = fmaf(wv[i], rs, acc);
        }
        op[(gy0 + 2 + row) * WW + (gx0 + 2 + threadIdx.x)] = acc * inv_s2;
    }
}

// ---------------- Kernel 2: constant-offset deformable conv ----------------
// Grid: (WW/TW, HH/TH, BB). Block: 256 threads = 8 warps; warp = one tile row,
// lane = x within row. Each thread computes all 32 output channels of one pixel,
// accumulated as 16 packed f32x2 (output-channel pairs).
__global__ __launch_bounds__(256, 1) void deform_kernel(const float* __restrict__ sigp,
                                                        const float* __restrict__ weight,
                                                        float* __restrict__ out) {
    extern __shared__ float smem[];
    float* sb = smem;                 // [CC][SB_ROWS][SB_COLS] zero-padded halo
    float* sw = smem + SB_FLOATS;     // [9][32 c][32 o]

    const int b   = blockIdx.z;
    const int by0 = blockIdx.y * TH;
    const int bx0 = blockIdx.x * TW;
    const int tid = threadIdx.x;

    // Load blurred tile (+halo), zero-filled out of image. Zero-fill exactly
    // reproduces the reference's clamp-index x zero-weight OOB semantics.
    const float* gp = g_blur + (size_t)b * CC * HH * WW;
    for (int idx = tid; idx < SB_FLOATS; idx += 256) {
        int c = idx / SB_PLANE;
        int rem = idx - c * SB_PLANE;
        int r = rem / SB_COLS;
        int q = rem - r * SB_COLS;
        int gy = by0 - HALO + r;
        int gx = bx0 - HALO + q;
        float v = 0.f;
        if (gy >= 0 && gy < HH && gx >= 0 && gx < WW)
            v = gp[c * (HH * WW) + gy * WW + gx];
        sb[idx] = v;
    }
    // Load weights reordered [o][c][ky][kx] -> [k][c][o] (o contiguous for LDS.64 pairs)
    for (int idx = tid; idx < SW_FLOATS; idx += 256) {
        int o = idx / 288;
        int rem = idx - o * 288;
        int c = rem / 9;
        int k = rem - c * 9;
        sw[(k * 32 + c) * 32 + o] = weight[idx];
    }
    __syncthreads();

    const float sigrate = (*sigp) * 6.0f;
    const int lane = tid & 31;
    const int wrow = tid >> 5;
    const int gy = by0 + wrow;
    const int gx = bx0 + lane;

    unsigned long long acc[16];
#pragma unroll
    for (int j = 0; j < 16; j++) acc[j] = 0ull;

    for (int k = 0; k < 9; k++) {
        const int kyi = k / 3 - 1;
        const int kxi = k - (k / 3) * 3 - 1;
        const float n2 = (float)(kyi * kyi + kxi * kxi);
        const float inv = (n2 > 0.f) ? (1.f / sqrtf(n2)) : 0.f;
        const float dy = (float)kyi + sigrate * ((float)kyi * inv);
        const float dx = (float)kxi + sigrate * ((float)kxi * inv);

        const float py = (float)gy + dy;
        const float px = (float)gx + dx;
        const float fy = floorf(py);
        const float fx = floorf(px);
        const float ty = py - fy;
        const float tx = px - fx;
        int ly = (int)fy - (by0 - HALO);
        int lx = (int)fx - (bx0 - HALO);
        ly = max(0, min(ly, SB_ROWS - 2));   // safety clamp; inactive at sigma=1
        lx = max(0, min(lx, SB_COLS - 2));
        const float wy0 = 1.f - ty, wy1 = ty;
        const float wx0 = 1.f - tx, wx1 = tx;
        const float w00 = wy0 * wx0, w01 = wy0 * wx1;
        const float w10 = wy1 * wx0, w11 = wy1 * wx1;

        const float* pbase = sb + ly * SB_COLS + lx;
        const unsigned long long* wk =
            reinterpret_cast<const unsigned long long*>(sw + k * 1024);

#pragma unroll 4
        for (int c = 0; c < 32; c++) {
            const float* p = pbase + c * SB_PLANE;
            float v = w00 * p[0];
            v = fmaf(w01, p[1], v);
            v = fmaf(w10, p[SB_COLS], v);
            v = fmaf(w11, p[SB_COLS + 1], v);
            const unsigned long long v2 = pack2(v, v);
            const unsigned long long* wc = wk + c * 16;
#pragma unroll
            for (int j = 0; j < 16; j++) acc[j] = fma2(v2, wc[j], acc[j]);
        }
    }

    float* ob = out + (size_t)b * OO * HH * WW + gy * WW + gx;
#pragma unroll
    for (int j = 0; j < 16; j++) {
        float lo, hi;
        unpack2(acc[j], lo, hi);
        ob[(size_t)(2 * j) * (HH * WW)] = lo;
        ob[(size_t)(2 * j + 1) * (HH * WW)] = hi;
    }
}

extern "C" void kernel_launch(void* const* d_in, const int* in_sizes, int n_in,
                              void* d_out, int out_size) {
    // Defensive input mapping by element count: x=33554432, sigma=1, weight=9216
    const float* x = nullptr;
    const float* sig = nullptr;
    const float* wgt = nullptr;
    for (int i = 0; i < n_in; i++) {
        if (in_sizes[i] == 1) sig = (const float*)d_in[i];
        else if (in_sizes[i] == OO * CC * 9) wgt = (const float*)d_in[i];
        else x = (const float*)d_in[i];
    }
    float* out = (float*)d_out;

    dim3 bgrid(WW / 32, HH / 32, BB * CC);
    blur_kernel<<<bgrid, dim3(32, 8)>>>(x, sig);

    cudaFuncSetAttribute(deform_kernel,
                         cudaFuncAttributeMaxDynamicSharedMemorySize, DEFORM_SMEM);
    dim3 dgrid(WW / TW, HH / TH, BB);
    deform_kernel<<<dgrid, 256, DEFORM_SMEM>>>(sig, wgt, out);
}

// round 2
// speedup vs baseline: 1.2238x; 1.2238x over previous
#include <cuda_runtime.h>

#define HH 256
#define WW 256
#define BB 16
#define CC 32
#define OO 32

#define TH 8            // tile rows
#define TW 64           // tile cols
#define HALO 8
#define CCH 8           // channel chunk
#define SB_ROWS (TH + 2*HALO)            // 24
#define SB_COLS (TW + 2*HALO)            // 80
#define SB_FLOATS (CCH * SB_ROWS * SB_COLS)   // 15360
#define VSTRIDE (TH*TW + 8)              // 520 (16B-aligned rows, bank-shifted)
#define VT_FLOATS (CCH * VSTRIDE)        // 4160
#define SWD_U64 (9 * CCH * 32)           // 2304
#define DEFORM_SMEM ((SB_FLOATS + 2*VT_FLOATS) * 4 + SWD_U64 * 8)  // 113152 B

// Scratch for the blurred image (B,C,H,W) fp32
__device__ float g_blur[(size_t)BB * CC * HH * WW];

typedef unsigned long long ull;

__device__ __forceinline__ ull pack2(float lo, float hi) {
    ull r;
    asm("mov.b64 %0, {%1, %2};" : "=l"(r) : "f"(lo), "f"(hi));
    return r;
}
__device__ __forceinline__ ull fma2(ull a, ull b, ull c) {
    ull d;
    asm("fma.rn.f32x2 %0, %1, %2, %3;" : "=l"(d) : "l"(a), "l"(b), "l"(c));
    return d;
}
__device__ __forceinline__ void unpack2(ull v, float& lo, float& hi) {
    asm("mov.b64 {%0, %1}, %2;" : "=f"(lo), "=f"(hi) : "l"(v));
}

// ---------------- Kernel 1: 5x5 gaussian blur (depthwise, SAME/zero pad) ----------------
__global__ __launch_bounds__(256) void blur_kernel(const float* __restrict__ x,
                                                   const float* __restrict__ sigp) {
    __shared__ float tile[36][36];
    const float sigma = *sigp;
    float wv[5];
    float s = 0.f;
#pragma unroll
    for (int i = 0; i < 5; i++) {
        float cc = (float)(i - 2);
        wv[i] = expf(-cc * cc / (2.f * sigma * sigma));
        s += wv[i];
    }
    const float inv_s2 = 1.f / (s * s);

    const int plane = blockIdx.z;                  // b*CC + c
    const int gy0 = blockIdx.y * 32 - 2;
    const int gx0 = blockIdx.x * 32 - 2;
    const float* xp = x + (size_t)plane * (HH * WW);
    const int tid = threadIdx.x + threadIdx.y * 32;  // block (32,8)

    for (int idx = tid; idx < 36 * 36; idx += 256) {
        int r = idx / 36, q = idx - r * 36;
        int gy = gy0 + r, gx = gx0 + q;
        float v = 0.f;
        if (gy >= 0 && gy < HH && gx >= 0 && gx < WW) v = xp[gy * WW + gx];
        tile[r][q] = v;
    }
    __syncthreads();

    float* op = g_blur + (size_t)plane * (HH * WW);
#pragma unroll
    for (int ry = 0; ry < 4; ry++) {
        const int row = threadIdx.y + ry * 8;
        float acc = 0.f;
#pragma unroll
        for (int i = 0; i < 5; i++) {
            float rs = 0.f;
#pragma unroll
            for (int j = 0; j < 5; j++)
                rs = fmaf(wv[j], tile[row + i][threadIdx.x + j], rs);
            acc = fmaf(wv[i], rs, acc);
        }
        op[(gy0 + 2 + row) * WW + (gx0 + 2 + threadIdx.x)] = acc * inv_s2;
    }
}

// ---------------- Kernel 2: constant-offset deformable conv ----------------
// Block: 256 threads, tile TH x TW = 512 pixels of one batch image.
// Channels processed in chunks of 8. Per tap: phase A stages bilinear-shifted
// values v[c][pix] into smem (double-buffered), phase B does a register-blocked
// channel-mix GEMM: each thread owns 8 output channels x 8 pixels (acc as
// pixel-pair f32x2), weights pre-duplicated (w,w) in smem.
__global__ __launch_bounds__(256, 2) void deform_kernel(const float* __restrict__ sigp,
                                                        const float* __restrict__ weight,
                                                        float* __restrict__ out) {
    extern __shared__ __align__(16) float smem[];
    float* sb = smem;                                  // [CCH][SB_ROWS][SB_COLS], zero halo
    float* vt = smem + SB_FLOATS;                      // [2][CCH][VSTRIDE]
    ull*   swd = (ull*)(smem + SB_FLOATS + 2 * VT_FLOATS);  // [9][CCH][32] dup pairs

    const int b   = blockIdx.z;
    const int by0 = blockIdx.y * TH;
    const int bx0 = blockIdx.x * TW;
    const int tid  = threadIdx.x;
    const int lane = tid & 31;
    const int warp = tid >> 5;

    const float sigrate = (*sigp) * 6.0f;

    // phase-B ownership: og -> 8 output channels, pg -> 8 contiguous pixels
    const int og   = tid & 3;
    const int pg   = tid >> 2;        // 0..63
    const int prow = pg >> 3;         // 0..7
    const int pcol = (pg & 7) * 8;    // 0..56

    ull acc[8][4];
#pragma unroll
    for (int j = 0; j < 8; j++)
#pragma unroll
        for (int p = 0; p < 4; p++) acc[j][p] = 0ull;

    for (int cc = 0; cc < CC / CCH; cc++) {
        __syncthreads();  // protect sb/swd (and vt) reuse across chunks

        // ---- load input chunk tile with zero halo (image-OOB -> 0) ----
        const float* gp = g_blur + ((size_t)b * CC + cc * CCH) * (HH * WW);
        for (int idx = tid; idx < SB_FLOATS; idx += 256) {
            int ci  = idx / (SB_ROWS * SB_COLS);
            int rem = idx - ci * (SB_ROWS * SB_COLS);
            int r = rem / SB_COLS;
            int q = rem - r * SB_COLS;
            int gy = by0 - HALO + r;
            int gx = bx0 - HALO + q;
            float v = 0.f;
            if (gy >= 0 && gy < HH && gx >= 0 && gx < WW)
                v = gp[ci * (HH * WW) + gy * WW + gx];
            sb[idx] = v;
        }
        // ---- load weight chunk, duplicated into (w,w) u64 ----
        for (int idx = tid; idx < SWD_U64; idx += 256) {
            int o   = idx & 31;
            int rem = idx >> 5;       // k*CCH + ci
            int ci  = rem & (CCH - 1);
            int k   = rem >> 3;
            float w = weight[(o * CC + cc * CCH + ci) * 9 + k];
            swd[idx] = pack2(w, w);
        }
        __syncthreads();

        for (int k = 0; k < 9; k++) {
            // ---- uniform tap geometry ----
            const int kyi = k / 3 - 1;
            const int kxi = k % 3 - 1;
            const float n2 = (float)(kyi * kyi + kxi * kxi);
            const float inv = (n2 > 0.f) ? (1.0f / sqrtf(n2)) : 0.0f;
            const float dy = (float)kyi + sigrate * ((float)kyi * inv);
            const float dx = (float)kxi + sigrate * ((float)kxi * inv);
            const float fy = floorf(dy), fx = floorf(dx);
            int iy = (int)fy, ix = (int)fx;
            const float ty = dy - fy, tx = dx - fx;
            iy = max(-HALO, min(iy, HALO - 1));   // safety clamp (inactive at sigma=1)
            ix = max(-HALO, min(ix, HALO - 1));
            const float w00 = (1.f - ty) * (1.f - tx);
            const float w01 = (1.f - ty) * tx;
            const float w10 = ty * (1.f - tx);
            const float w11 = ty * tx;
            const bool hx = (tx != 0.f);
            const bool hy = (ty != 0.f);

            float* vbuf = vt + (k & 1) * VT_FLOATS;

            // ---- phase A: stage shifted tile (uniform-branch skips for t==0) ----
            for (int it = warp; it < CCH * TH; it += 8) {
                const int ci = it >> 3;
                const int row = it & (TH - 1);
                const float* base = sb + (ci * SB_ROWS + row + HALO + iy) * SB_COLS
                                      + HALO + ix;
                float* vrow = vbuf + ci * VSTRIDE + row * TW;
#pragma unroll
                for (int xx0 = 0; xx0 < TW; xx0 += 32) {
                    const int xx = xx0 + lane;
                    float v = w00 * base[xx];
                    if (hx) v = fmaf(w01, base[xx + 1], v);
                    if (hy) {
                        v = fmaf(w10, base[SB_COLS + xx], v);
                        if (hx) v = fmaf(w11, base[SB_COLS + xx + 1], v);
                    }
                    vrow[xx] = v;
                }
            }
            __syncthreads();

            // ---- phase B: register-blocked 8 och x 8 pix GEMM over this chunk ----
            const ull* wk = swd + (k * CCH) * 32 + og * 8;
#pragma unroll
            for (int ci = 0; ci < CCH; ci++) {
                const ull* vp = (const ull*)(vbuf + ci * VSTRIDE + prow * TW + pcol);
                const ull v0 = vp[0], v1 = vp[1], v2 = vp[2], v3 = vp[3];
                const ull* wp = wk + ci * 32;
#pragma unroll
                for (int j = 0; j < 8; j++) {
                    const ull w = wp[j];
                    acc[j][0] = fma2(v0, w, acc[j][0]);
                    acc[j][1] = fma2(v1, w, acc[j][1]);
                    acc[j][2] = fma2(v2, w, acc[j][2]);
                    acc[j][3] = fma2(v3, w, acc[j][3]);
                }
            }
        }
    }

    // ---- epilogue: 8 och x 8 pixels per thread, vectorized stores ----
    float* ob = out + ((size_t)b * OO + og * 8) * (HH * WW)
                    + (by0 + prow) * WW + bx0 + pcol;
#pragma unroll
    for (int j = 0; j < 8; j++) {
        float4 f0, f1;
        unpack2(acc[j][0], f0.x, f0.y);
        unpack2(acc[j][1], f0.z, f0.w);
        unpack2(acc[j][2], f1.x, f1.y);
        unpack2(acc[j][3], f1.z, f1.w);
        float* p = ob + (size_t)j * (HH * WW);
        ((float4*)p)[0] = f0;
        ((float4*)p)[1] = f1;
    }
}

extern "C" void kernel_launch(void* const* d_in, const int* in_sizes, int n_in,
                              void* d_out, int out_size) {
    const float* x = nullptr;
    const float* sig = nullptr;
    const float* wgt = nullptr;
    for (int i = 0; i < n_in; i++) {
        if (in_sizes[i] == 1) sig = (const float*)d_in[i];
        else if (in_sizes[i] == OO * CC * 9) wgt = (const float*)d_in[i];
        else x = (const float*)d_in[i];
    }
    float* out = (float*)d_out;

    dim3 bgrid(WW / 32, HH / 32, BB * CC);
    blur_kernel<<<bgrid, dim3(32, 8)>>>(x, sig);

    cudaFuncSetAttribute(deform_kernel,
                         cudaFuncAttributeMaxDynamicSharedMemorySize, DEFORM_SMEM);
    dim3 dgrid(WW / TW, HH / TH, BB);
    deform_kernel<<<dgrid, 256, DEFORM_SMEM>>>(sig, wgt, out);
}